// round 14
// baseline (speedup 1.0000x reference)
#include <cuda_runtime.h>
#include <cuda_bf16.h>
#include <cstdint>

#define T_LEN 4096
#define HID   1024
#define EMB   1024
#define NTAG  50257
#define NLSTM 64          // LSTM blocks (SMs)
#define NWORK 84          // dedicated GEMM worker blocks
#define NTILM 16          // 4096/256
#define NTILN 393         // ceil(50257/128)
#define TOT_TILES (NTILM * NTILN)

// ---------------- scratch (device globals; no allocation allowed) ----------------
__device__ __align__(16) float          g_Gx[(size_t)T_LEN * 4 * HID];      // 64 MB gate preacts
__device__ __align__(16) __nv_bfloat16 g_xbf[(size_t)T_LEN * EMB];         // 8 MB
__device__ __align__(16) __nv_bfloat16 g_wxbf[(size_t)4 * HID * EMB];      // 8 MB
__device__ __align__(16) float          g_biascat[4 * HID];
__device__ __align__(16) __nv_bfloat16 g_wtbf[(size_t)NTAG * HID];         // 103 MB
__device__ __align__(16) __nv_bfloat16 g_hbf[(size_t)T_LEN * HID];         // 8 MB lstm_out bf16
__device__ __align__(16) float          g_hbuf[2][HID];                     // ping-pong h
__device__ __align__(16) float          g_rowsum[T_LEN];                    // fused softmax sums
__device__ unsigned                     g_ctr;     // LSTM barrier counter (also progress)
__device__ unsigned                     g_tileq;   // GEMM tile queue

// ---------------- small helpers ----------------
__device__ __forceinline__ uint32_t smem_u32(const void* p) {
    return (uint32_t)__cvta_generic_to_shared(p);
}
__device__ __forceinline__ void cp16(uint32_t dst, const void* src, int bytes) {
    asm volatile("cp.async.cg.shared.global [%0], [%1], 16, %2;\n"
                 :: "r"(dst), "l"(src), "r"(bytes));
}
__device__ __forceinline__ void cp_commit() { asm volatile("cp.async.commit_group;\n"); }
template <int N> __device__ __forceinline__ void cp_wait() {
    asm volatile("cp.async.wait_group %0;\n" :: "n"(N));
}
__device__ __forceinline__ void ldsm4(uint32_t* r, uint32_t addr) {
    asm volatile("ldmatrix.sync.aligned.m8n8.x4.shared.b16 {%0,%1,%2,%3}, [%4];\n"
                 : "=r"(r[0]), "=r"(r[1]), "=r"(r[2]), "=r"(r[3]) : "r"(addr));
}
__device__ __forceinline__ void mma16816(float* d, const uint32_t* a, const uint32_t* b) {
    asm volatile(
        "mma.sync.aligned.m16n8k16.row.col.f32.bf16.bf16.f32 "
        "{%0,%1,%2,%3}, {%4,%5,%6,%7}, {%8,%9}, {%0,%1,%2,%3};\n"
        : "+f"(d[0]), "+f"(d[1]), "+f"(d[2]), "+f"(d[3])
        : "r"(a[0]), "r"(a[1]), "r"(a[2]), "r"(a[3]), "r"(b[0]), "r"(b[1]));
}
__device__ __forceinline__ float sigf(float x)  { return 1.0f / (1.0f + __expf(-x)); }
__device__ __forceinline__ float tanhfast(float x) { return 2.0f / (1.0f + __expf(-2.0f * x)) - 1.0f; }

// ---------------- merged prep (single launch) ----------------
__global__ void prep_all(const int* __restrict__ sentence, const float* __restrict__ emb,
                         const float* __restrict__ Wf, const float* __restrict__ Wi,
                         const float* __restrict__ Wg, const float* __restrict__ Wo,
                         const float* __restrict__ bfv, const float* __restrict__ biv,
                         const float* __restrict__ bgv, const float* __restrict__ bov,
                         const float* __restrict__ Wt) {
    const int blk = blockIdx.x, tid = threadIdx.x;
    if (blk < 4096) {
        const float* src = emb + (size_t)sentence[blk] * EMB;
        for (int e = tid; e < EMB; e += 256)
            g_xbf[(size_t)blk * EMB + e] = __float2bfloat16(src[e]);
        if (tid == 0) g_rowsum[blk] = 0.f;
    } else if (blk < 8192) {
        int r = blk - 4096;
        int gate = r >> 10, j = r & 1023;
        const float* W  = (gate == 0) ? Wf  : (gate == 1) ? Wi  : (gate == 2) ? Wg  : Wo;
        const float* bb = (gate == 0) ? bfv : (gate == 1) ? biv : (gate == 2) ? bgv : bov;
        for (int k = tid; k < EMB; k += 256)
            g_wxbf[(size_t)r * EMB + k] = __float2bfloat16(W[(size_t)j * (EMB + HID) + k]);
        if (tid == 0) g_biascat[r] = bb[j];
    } else if (blk < 16384) {
        size_t total = (size_t)NTAG * HID;
        for (size_t i = (size_t)(blk - 8192) * 256 + tid; i < total; i += (size_t)8192 * 256)
            g_wtbf[i] = __float2bfloat16(Wt[i]);
    } else {
        for (int i = tid; i < HID; i += 256) { g_hbuf[0][i] = 0.f; g_hbuf[1][i] = 0.f; }
        if (tid == 0) { g_ctr = 0u; g_tileq = 0u; }
    }
}

// ---------------- standalone bf16 GEMM for Gx (R13 version) ----------------
#define GLDS 40
#define A_ST (256 * GLDS)
#define B_ST (128 * GLDS)
static constexpr int GEMM_SMEM = 3 * (A_ST + B_ST) * 2;   // 92160 B

__global__ void __launch_bounds__(512, 1) gemm_bf16(
    const __nv_bfloat16* __restrict__ A, const __nv_bfloat16* __restrict__ B,
    const float* __restrict__ bias, float* __restrict__ C, int M, int N, int K) {
    extern __shared__ __align__(16) __nv_bfloat16 sm[];
    __nv_bfloat16* As = sm;
    __nv_bfloat16* Bs = sm + 3 * A_ST;

    const int tid = threadIdx.x, lane = tid & 31, warp = tid >> 5;

    int lin = blockIdx.y * gridDim.x + blockIdx.x;
    int grp = lin / (gridDim.x * 4);
    int within = lin % (gridDim.x * 4);
    int tm = grp * 4 + (within & 3);
    int tn = within >> 2;
    const int bm = tm * 256, bn = tn * 128;

    const int wm = (warp >> 2) * 64, wn = (warp & 3) * 32;

    float acc[4][4][4];
#pragma unroll
    for (int a = 0; a < 4; a++)
#pragma unroll
        for (int b = 0; b < 4; b++)
#pragma unroll
            for (int c = 0; c < 4; c++) acc[a][b][c] = 0.f;

    auto loadA = [&](int st, int k0) {
#pragma unroll
        for (int i = 0; i < 2; i++) {
            int idx = tid + 512 * i, row = idx >> 2, cq = idx & 3;
            cp16(smem_u32(&As[st * A_ST + row * GLDS + cq * 8]),
                 A + (size_t)(bm + row) * K + k0 + cq * 8, 16);
        }
    };
    auto loadB = [&](int st, int k0) {
        int row = tid >> 2, cq = tid & 3;
        int nr = bn + row;
        const __nv_bfloat16* src = B + (size_t)(nr < N ? nr : 0) * K + k0 + cq * 8;
        cp16(smem_u32(&Bs[st * B_ST + row * GLDS + cq * 8]), src, nr < N ? 16 : 0);
    };

    const int NK = K / 32;
    loadA(0, 0);  loadB(0, 0);  cp_commit();
    loadA(1, 32); loadB(1, 32); cp_commit();

    for (int ks = 0; ks < NK; ks++) {
        const int st = ks % 3;
        if (ks + 1 < NK) cp_wait<1>(); else cp_wait<0>();
        __syncthreads();
#pragma unroll
        for (int kk = 0; kk < 2; kk++) {
            uint32_t af[4][4];
#pragma unroll
            for (int mt = 0; mt < 4; mt++) {
                uint32_t addr = smem_u32(
                    &As[st * A_ST + (wm + mt * 16 + (lane & 15)) * GLDS + kk * 16 + (lane >> 4) * 8]);
                ldsm4(af[mt], addr);
            }
            uint32_t bfr[8];
#pragma unroll
            for (int q = 0; q < 2; q++) {
                int row = wn + q * 16 + ((lane >> 4) << 3) + (lane & 7);
                int col = kk * 16 + ((lane >> 3) & 1) * 8;
                ldsm4(&bfr[q * 4], smem_u32(&Bs[st * B_ST + row * GLDS + col]));
            }
#pragma unroll
            for (int mt = 0; mt < 4; mt++)
#pragma unroll
                for (int nt = 0; nt < 4; nt++) mma16816(acc[mt][nt], af[mt], &bfr[nt * 2]);
        }
        if (ks + 2 < NK) {
            loadA((ks + 2) % 3, (ks + 2) * 32);
            loadB((ks + 2) % 3, (ks + 2) * 32);
            cp_commit();
        }
    }

#pragma unroll
    for (int mt = 0; mt < 4; mt++) {
        int m0 = bm + wm + mt * 16 + (lane >> 2);
#pragma unroll
        for (int nt = 0; nt < 4; nt++) {
            int n0 = bn + wn + nt * 8 + (lane & 3) * 2;
            float* p0 = C + (size_t)m0 * N + n0;
            float* p1 = C + (size_t)(m0 + 8) * N + n0;
            if (n0 < N) {
                float bv = __ldg(bias + n0);
                p0[0] = acc[mt][nt][0] + bv;
                p1[0] = acc[mt][nt][2] + bv;
            }
            if (n0 + 1 < N) {
                float bv = __ldg(bias + n0 + 1);
                p0[1] = acc[mt][nt][1] + bv;
                p1[1] = acc[mt][nt][3] + bv;
            }
        }
    }
}

// ---------------- fused: partitioned LSTM (blocks 0-63) + GEMM workers (64-147) ----------------
// 148 CTAs x 512 threads, 92KB dynamic smem, launch_bounds(512,1) => exactly
// 1 CTA/SM: hard SM partitioning, no co-residency with the LSTM critical path.
// LSTM: warp w owns unit j=16*bid+w (all 4 gates), bf16x2 weights in 64 regs.
// Barrier: red.release on g_ctr (64 arrivals) + acquire/backoff spin.
// Workers: steal 256x128 logits tiles m-stripe-major, gated on g_ctr progress;
// finished LSTM blocks join the worker pool for a full-chip tail.
__global__ void __launch_bounds__(512, 1) fused_lstm_gemm(
    const float* __restrict__ Wf, const float* __restrict__ Wi,
    const float* __restrict__ Wg, const float* __restrict__ Wo,
    const float* __restrict__ bias_t, float* __restrict__ C) {
    extern __shared__ __align__(16) __nv_bfloat16 dsm[];
    const int bid = blockIdx.x, tid = threadIdx.x;
    const int lane = tid & 31, warp = tid >> 5;

    if (bid < NLSTM) {
        // ================= LSTM role =================
        const int j = bid * 16 + warp;
        const size_t roff = (size_t)j * (EMB + HID) + EMB;

        // pack recurrent weights: pair (k, k+32) with k = lane + 64p
        uint32_t wfq[16], wiq[16], wgq[16], woq[16];
#pragma unroll
        for (int p = 0; p < 16; p++) {
            int k0 = lane + 64 * p, k1 = k0 + 32;
            __nv_bfloat162 t2;
            t2 = __floats2bfloat162_rn(Wf[roff + k0], Wf[roff + k1]); wfq[p] = *(uint32_t*)&t2;
            t2 = __floats2bfloat162_rn(Wi[roff + k0], Wi[roff + k1]); wiq[p] = *(uint32_t*)&t2;
            t2 = __floats2bfloat162_rn(Wg[roff + k0], Wg[roff + k1]); wgq[p] = *(uint32_t*)&t2;
            t2 = __floats2bfloat162_rn(Wo[roff + k0], Wo[roff + k1]); woq[p] = *(uint32_t*)&t2;
        }

        float* sh_h = (float*)dsm;   // 1024 floats

        const float* gxp = g_Gx + (size_t)0 * (4 * HID) + j;
        float gx_f = __ldg(gxp);
        float gx_i = __ldg(gxp + HID);
        float gx_g = __ldg(gxp + 2 * HID);
        float gx_o = __ldg(gxp + 3 * HID);

        float c = 0.f;
        for (int t = 0; t < T_LEN; t++) {
            const int p = t & 1;
            {
                const float2* hb = (const float2*)g_hbuf[p];
                float2 hv = __ldcv(hb + tid);
                ((float2*)sh_h)[tid] = hv;
            }
            __syncthreads();

            float sf = 0.f, si = 0.f, sg = 0.f, so = 0.f;
#pragma unroll
            for (int q = 0; q < 16; q++) {
                float h0 = sh_h[lane + 64 * q];
                float h1 = sh_h[lane + 64 * q + 32];
                float2 w2;
                w2 = __bfloat1622float2(*(__nv_bfloat162*)&wfq[q]);
                sf = fmaf(w2.x, h0, fmaf(w2.y, h1, sf));
                w2 = __bfloat1622float2(*(__nv_bfloat162*)&wiq[q]);
                si = fmaf(w2.x, h0, fmaf(w2.y, h1, si));
                w2 = __bfloat1622float2(*(__nv_bfloat162*)&wgq[q]);
                sg = fmaf(w2.x, h0, fmaf(w2.y, h1, sg));
                w2 = __bfloat1622float2(*(__nv_bfloat162*)&woq[q]);
                so = fmaf(w2.x, h0, fmaf(w2.y, h1, so));
            }
#pragma unroll
            for (int off = 16; off; off >>= 1) {
                sf += __shfl_xor_sync(0xffffffffu, sf, off);
                si += __shfl_xor_sync(0xffffffffu, si, off);
                sg += __shfl_xor_sync(0xffffffffu, sg, off);
                so += __shfl_xor_sync(0xffffffffu, so, off);
            }

            float fg = sigf(sf + gx_f);
            float ig = sigf(si + gx_i);
            float gg = tanhfast(sg + gx_g);
            float og = sigf(so + gx_o);
            c = fmaf(fg, c, ig * gg);
            float h = og * tanhfast(c);

            if (lane == 0) {
                g_hbuf[p ^ 1][j] = h;
                g_hbf[(size_t)t * HID + j] = __float2bfloat16(h);
            }

            if (t + 1 < T_LEN) {
                const float* gq = g_Gx + (size_t)(t + 1) * (4 * HID) + j;
                gx_f = __ldg(gq);
                gx_i = __ldg(gq + HID);
                gx_g = __ldg(gq + 2 * HID);
                gx_o = __ldg(gq + 3 * HID);
            }

            __syncthreads();
            if (tid == 0) {
                asm volatile("red.release.gpu.global.add.u32 [%0], 1;"
                             :: "l"(&g_ctr) : "memory");
                const unsigned target = (unsigned)(t + 1) * NLSTM;
                unsigned e;
                asm volatile("ld.acquire.gpu.global.u32 %0, [%1];"
                             : "=r"(e) : "l"(&g_ctr) : "memory");
                if (e < target) {
                    unsigned ns = 32;
                    do {
                        __nanosleep(ns);
                        if (ns < 256) ns <<= 1;
                        asm volatile("ld.acquire.gpu.global.u32 %0, [%1];"
                                     : "=r"(e) : "l"(&g_ctr) : "memory");
                    } while (e < target);
                }
            }
            __syncthreads();
        }
        // fall through: join the GEMM worker pool for the tail
        __syncthreads();
    }

    // ================= GEMM worker role =================
    __nv_bfloat16* As = dsm;               // [3][A_ST]
    __nv_bfloat16* Bs = dsm + 3 * A_ST;    // [3][B_ST]
    const int wm = (warp >> 2) * 64, wn = (warp & 3) * 32;
    __shared__ unsigned sh_tile;

    for (;;) {
        if (tid == 0) sh_tile = atomicAdd(&g_tileq, 1u);
        __syncthreads();
        const unsigned tile = sh_tile;
        __syncthreads();
        if (tile >= TOT_TILES) return;
        const int tm = tile / NTILN, tn = tile % NTILN;
        const int bm = tm * 256, bn = tn * 128;

        if (tid == 0) {
            const unsigned need = (unsigned)(bm + 256) * NLSTM;
            unsigned e;
            asm volatile("ld.acquire.gpu.global.u32 %0, [%1];"
                         : "=r"(e) : "l"(&g_ctr) : "memory");
            while (e < need) {
                __nanosleep(2048);
                asm volatile("ld.acquire.gpu.global.u32 %0, [%1];"
                             : "=r"(e) : "l"(&g_ctr) : "memory");
            }
        }
        __syncthreads();

        float acc[4][4][4];
#pragma unroll
        for (int a = 0; a < 4; a++)
#pragma unroll
            for (int b = 0; b < 4; b++)
#pragma unroll
                for (int cc = 0; cc < 4; cc++) acc[a][b][cc] = 0.f;

        auto loadA = [&](int st, int k0) {
#pragma unroll
            for (int i = 0; i < 2; i++) {
                int idx = tid + 512 * i, row = idx >> 2, cq = idx & 3;
                cp16(smem_u32(&As[st * A_ST + row * GLDS + cq * 8]),
                     g_hbf + (size_t)(bm + row) * HID + k0 + cq * 8, 16);
            }
        };
        auto loadB = [&](int st, int k0) {
            int row = tid >> 2, cq = tid & 3;
            int nr = bn + row;
            const __nv_bfloat16* src = g_wtbf + (size_t)(nr < NTAG ? nr : 0) * HID + k0 + cq * 8;
            cp16(smem_u32(&Bs[st * B_ST + row * GLDS + cq * 8]), src, nr < NTAG ? 16 : 0);
        };

        const int NK = HID / 32;   // 32
        loadA(0, 0);  loadB(0, 0);  cp_commit();
        loadA(1, 32); loadB(1, 32); cp_commit();

        for (int ks = 0; ks < NK; ks++) {
            const int st = ks % 3;
            if (ks + 1 < NK) cp_wait<1>(); else cp_wait<0>();
            __syncthreads();
#pragma unroll
            for (int kk = 0; kk < 2; kk++) {
                uint32_t af[4][4];
#pragma unroll
                for (int mt = 0; mt < 4; mt++) {
                    uint32_t addr = smem_u32(
                        &As[st * A_ST + (wm + mt * 16 + (lane & 15)) * GLDS + kk * 16 + (lane >> 4) * 8]);
                    ldsm4(af[mt], addr);
                }
                uint32_t bfr[8];
#pragma unroll
                for (int q = 0; q < 2; q++) {
                    int row = wn + q * 16 + ((lane >> 4) << 3) + (lane & 7);
                    int col = kk * 16 + ((lane >> 3) & 1) * 8;
                    ldsm4(&bfr[q * 4], smem_u32(&Bs[st * B_ST + row * GLDS + col]));
                }
#pragma unroll
                for (int mt = 0; mt < 4; mt++)
#pragma unroll
                    for (int nt = 0; nt < 4; nt++) mma16816(acc[mt][nt], af[mt], &bfr[nt * 2]);
            }
            if (ks + 2 < NK) {
                loadA((ks + 2) % 3, (ks + 2) * 32);
                loadB((ks + 2) % 3, (ks + 2) * 32);
                cp_commit();
            }
        }

        // epilogue with fused exp-sum
#pragma unroll
        for (int mt = 0; mt < 4; mt++) {
            int m0 = bm + wm + mt * 16 + (lane >> 2);
            float e0 = 0.f, e1 = 0.f;
#pragma unroll
            for (int nt = 0; nt < 4; nt++) {
                int n0 = bn + wn + nt * 8 + (lane & 3) * 2;
                float* p0 = C + (size_t)m0 * NTAG + n0;
                float* p1 = C + (size_t)(m0 + 8) * NTAG + n0;
                if (n0 < NTAG) {
                    float bv = __ldg(bias_t + n0);
                    float v00 = acc[mt][nt][0] + bv;
                    float v10 = acc[mt][nt][2] + bv;
                    p0[0] = v00;
                    p1[0] = v10;
                    e0 += __expf(v00); e1 += __expf(v10);
                }
                if (n0 + 1 < NTAG) {
                    float bv = __ldg(bias_t + n0 + 1);
                    float v01 = acc[mt][nt][1] + bv;
                    float v11 = acc[mt][nt][3] + bv;
                    p0[1] = v01;
                    p1[1] = v11;
                    e0 += __expf(v01); e1 += __expf(v11);
                }
            }
            e0 += __shfl_xor_sync(0xffffffffu, e0, 1);
            e0 += __shfl_xor_sync(0xffffffffu, e0, 2);
            e1 += __shfl_xor_sync(0xffffffffu, e1, 1);
            e1 += __shfl_xor_sync(0xffffffffu, e1, 2);
            if ((lane & 3) == 0) {
                atomicAdd(&g_rowsum[m0], e0);
                atomicAdd(&g_rowsum[m0 + 8], e1);
            }
        }
        __syncthreads();
    }
}

// ---------------- log_softmax finish ----------------
__global__ void logsoftmax_finish(float* __restrict__ C) {
    int r = blockIdx.x;
    float lse = __logf(g_rowsum[r]);
    float* row = C + (size_t)r * NTAG;
    for (int i = threadIdx.x; i < NTAG; i += 256) row[i] -= lse;
}

// ---------------- launch ----------------
extern "C" void kernel_launch(void* const* d_in, const int* in_sizes, int n_in,
                              void* d_out, int out_size) {
    const int*   sentence = (const int*)d_in[0];
    const float* emb  = (const float*)d_in[1];
    const float* Wf   = (const float*)d_in[2];
    const float* bf_  = (const float*)d_in[3];
    const float* Wi   = (const float*)d_in[4];
    const float* bi_  = (const float*)d_in[5];
    const float* Wg   = (const float*)d_in[6];
    const float* bg_  = (const float*)d_in[7];
    const float* Wo   = (const float*)d_in[8];
    const float* bo_  = (const float*)d_in[9];
    const float* Wt   = (const float*)d_in[10];
    const float* bt_  = (const float*)d_in[11];
    float* out = (float*)d_out;

    void *pGx, *pxbf, *pwxbf, *pbias;
    cudaGetSymbolAddress(&pGx, g_Gx);
    cudaGetSymbolAddress(&pxbf, g_xbf);
    cudaGetSymbolAddress(&pwxbf, g_wxbf);
    cudaGetSymbolAddress(&pbias, g_biascat);

    cudaFuncSetAttribute(gemm_bf16, cudaFuncAttributeMaxDynamicSharedMemorySize, GEMM_SMEM);
    cudaFuncSetAttribute(fused_lstm_gemm, cudaFuncAttributeMaxDynamicSharedMemorySize, GEMM_SMEM);

    prep_all<<<16385, 256>>>(sentence, emb, Wf, Wi, Wg, Wo, bf_, bi_, bg_, bo_, Wt);

    // Gx = x @ Wx^T + b : M=4096, N=4096, K=1024
    dim3 gA((4 * HID + 127) / 128, T_LEN / 256);
    gemm_bf16<<<gA, 512, GEMM_SMEM>>>((const __nv_bfloat16*)pxbf, (const __nv_bfloat16*)pwxbf,
                                      (const float*)pbias, (float*)pGx, T_LEN, 4 * HID, EMB);

    // partitioned LSTM (64 SMs) + overlapped logits GEMM (84 SMs) + full-chip tail
    fused_lstm_gemm<<<NLSTM + NWORK, 512, GEMM_SMEM>>>(Wf, Wi, Wg, Wo, bt_, out);

    logsoftmax_finish<<<T_LEN, 256>>>(out);
}

// round 15
// speedup vs baseline: 1.2943x; 1.2943x over previous
#include <cuda_runtime.h>
#include <cuda_bf16.h>
#include <cstdint>

#define T_LEN 4096
#define HID   1024
#define EMB   1024
#define NTAG  50257
#define NBLK  128   // persistent LSTM blocks

// ---------------- scratch (device globals; no allocation allowed) ----------------
__device__ __align__(16) float          g_Gx[(size_t)T_LEN * 4 * HID];      // 64 MB gate preacts
__device__ __align__(16) __nv_bfloat16 g_xbf[(size_t)T_LEN * EMB];         // 8 MB
__device__ __align__(16) __nv_bfloat16 g_wxbf[(size_t)4 * HID * EMB];      // 8 MB
__device__ __align__(16) float          g_biascat[4 * HID];
__device__ __align__(16) __nv_bfloat16 g_wtbf[(size_t)NTAG * HID];         // 103 MB
__device__ __align__(16) __nv_bfloat16 g_hbf[(size_t)T_LEN * HID];         // 8 MB lstm_out bf16
__device__ __align__(16) unsigned       g_htag[2][HID];                    // packed (tag16|bf16 h), ping-pong
__device__ __align__(16) float          g_rowsum[T_LEN];                   // fused softmax sums
__device__ unsigned                     g_ctr;   // unused (kept for layout stability)

// ---------------- small helpers ----------------
__device__ __forceinline__ uint32_t smem_u32(const void* p) {
    return (uint32_t)__cvta_generic_to_shared(p);
}
__device__ __forceinline__ void cp16(uint32_t dst, const void* src, int bytes) {
    asm volatile("cp.async.cg.shared.global [%0], [%1], 16, %2;\n"
                 :: "r"(dst), "l"(src), "r"(bytes));
}
__device__ __forceinline__ void cp_commit() { asm volatile("cp.async.commit_group;\n"); }
template <int N> __device__ __forceinline__ void cp_wait() {
    asm volatile("cp.async.wait_group %0;\n" :: "n"(N));
}
__device__ __forceinline__ void ldsm4(uint32_t* r, uint32_t addr) {
    asm volatile("ldmatrix.sync.aligned.m8n8.x4.shared.b16 {%0,%1,%2,%3}, [%4];\n"
                 : "=r"(r[0]), "=r"(r[1]), "=r"(r[2]), "=r"(r[3]) : "r"(addr));
}
__device__ __forceinline__ void mma16816(float* d, const uint32_t* a, const uint32_t* b) {
    asm volatile(
        "mma.sync.aligned.m16n8k16.row.col.f32.bf16.bf16.f32 "
        "{%0,%1,%2,%3}, {%4,%5,%6,%7}, {%8,%9}, {%0,%1,%2,%3};\n"
        : "+f"(d[0]), "+f"(d[1]), "+f"(d[2]), "+f"(d[3])
        : "r"(a[0]), "r"(a[1]), "r"(a[2]), "r"(a[3]), "r"(b[0]), "r"(b[1]));
}
__device__ __forceinline__ float sigf(float x)  { return 1.0f / (1.0f + __expf(-x)); }
__device__ __forceinline__ float tanhfast(float x) { return 2.0f / (1.0f + __expf(-2.0f * x)) - 1.0f; }

// ---------------- merged prep (single launch) ----------------
__global__ void prep_all(const int* __restrict__ sentence, const float* __restrict__ emb,
                         const float* __restrict__ Wf, const float* __restrict__ Wi,
                         const float* __restrict__ Wg, const float* __restrict__ Wo,
                         const float* __restrict__ bfv, const float* __restrict__ biv,
                         const float* __restrict__ bgv, const float* __restrict__ bov,
                         const float* __restrict__ Wt) {
    const int blk = blockIdx.x, tid = threadIdx.x;
    if (blk < 4096) {
        const float* src = emb + (size_t)sentence[blk] * EMB;
        for (int e = tid; e < EMB; e += 256)
            g_xbf[(size_t)blk * EMB + e] = __float2bfloat16(src[e]);
        if (tid == 0) g_rowsum[blk] = 0.f;
    } else if (blk < 8192) {
        int r = blk - 4096;
        int gate = r >> 10, j = r & 1023;
        const float* W  = (gate == 0) ? Wf  : (gate == 1) ? Wi  : (gate == 2) ? Wg  : Wo;
        const float* bb = (gate == 0) ? bfv : (gate == 1) ? biv : (gate == 2) ? bgv : bov;
        for (int k = tid; k < EMB; k += 256)
            g_wxbf[(size_t)r * EMB + k] = __float2bfloat16(W[(size_t)j * (EMB + HID) + k]);
        if (tid == 0) g_biascat[r] = bb[j];
    } else if (blk < 16384) {
        size_t total = (size_t)NTAG * HID;
        for (size_t i = (size_t)(blk - 8192) * 256 + tid; i < total; i += (size_t)8192 * 256)
            g_wtbf[i] = __float2bfloat16(Wt[i]);
    } else {
        for (int i = tid; i < HID; i += 256) {
            g_htag[0][i] = 0u;            // tag 0, h = bf16(0)
            g_htag[1][i] = 0xFFFF0000u;   // invalid tag
        }
        if (tid == 0) g_ctr = 0u;
    }
}

// ---------------- bf16 GEMM:  C[m,n] = sum_k A[m,k]*B[n,k] + bias[n] ----------------
// (identical to R13: 256x128x32, 3-stage, 512 thr, supertile swizzle, opt. exp-sum)
#define GLDS 40
#define A_ST (256 * GLDS)
#define B_ST (128 * GLDS)
static constexpr int GEMM_SMEM = 3 * (A_ST + B_ST) * 2;   // 92160 B

__global__ void __launch_bounds__(512, 1) gemm_bf16(
    const __nv_bfloat16* __restrict__ A, const __nv_bfloat16* __restrict__ B,
    const float* __restrict__ bias, float* __restrict__ C, int M, int N, int K,
    float* __restrict__ rowsum) {
    extern __shared__ __align__(16) __nv_bfloat16 sm[];
    __nv_bfloat16* As = sm;
    __nv_bfloat16* Bs = sm + 3 * A_ST;

    const int tid = threadIdx.x, lane = tid & 31, warp = tid >> 5;

    int lin = blockIdx.y * gridDim.x + blockIdx.x;
    int grp = lin / (gridDim.x * 4);
    int within = lin % (gridDim.x * 4);
    int tm = grp * 4 + (within & 3);
    int tn = within >> 2;
    const int bm = tm * 256, bn = tn * 128;

    const int wm = (warp >> 2) * 64, wn = (warp & 3) * 32;

    float acc[4][4][4];
#pragma unroll
    for (int a = 0; a < 4; a++)
#pragma unroll
        for (int b = 0; b < 4; b++)
#pragma unroll
            for (int c = 0; c < 4; c++) acc[a][b][c] = 0.f;

    auto loadA = [&](int st, int k0) {
#pragma unroll
        for (int i = 0; i < 2; i++) {
            int idx = tid + 512 * i, row = idx >> 2, cq = idx & 3;
            cp16(smem_u32(&As[st * A_ST + row * GLDS + cq * 8]),
                 A + (size_t)(bm + row) * K + k0 + cq * 8, 16);
        }
    };
    auto loadB = [&](int st, int k0) {
        int row = tid >> 2, cq = tid & 3;
        int nr = bn + row;
        const __nv_bfloat16* src = B + (size_t)(nr < N ? nr : 0) * K + k0 + cq * 8;
        cp16(smem_u32(&Bs[st * B_ST + row * GLDS + cq * 8]), src, nr < N ? 16 : 0);
    };

    const int NK = K / 32;
    loadA(0, 0);  loadB(0, 0);  cp_commit();
    loadA(1, 32); loadB(1, 32); cp_commit();

    for (int ks = 0; ks < NK; ks++) {
        const int st = ks % 3;
        if (ks + 1 < NK) cp_wait<1>(); else cp_wait<0>();
        __syncthreads();
#pragma unroll
        for (int kk = 0; kk < 2; kk++) {
            uint32_t af[4][4];
#pragma unroll
            for (int mt = 0; mt < 4; mt++) {
                uint32_t addr = smem_u32(
                    &As[st * A_ST + (wm + mt * 16 + (lane & 15)) * GLDS + kk * 16 + (lane >> 4) * 8]);
                ldsm4(af[mt], addr);
            }
            uint32_t bfr[8];
#pragma unroll
            for (int q = 0; q < 2; q++) {
                int row = wn + q * 16 + ((lane >> 4) << 3) + (lane & 7);
                int col = kk * 16 + ((lane >> 3) & 1) * 8;
                ldsm4(&bfr[q * 4], smem_u32(&Bs[st * B_ST + row * GLDS + col]));
            }
#pragma unroll
            for (int mt = 0; mt < 4; mt++)
#pragma unroll
                for (int nt = 0; nt < 4; nt++) mma16816(acc[mt][nt], af[mt], &bfr[nt * 2]);
        }
        if (ks + 2 < NK) {
            loadA((ks + 2) % 3, (ks + 2) * 32);
            loadB((ks + 2) % 3, (ks + 2) * 32);
            cp_commit();
        }
    }

#pragma unroll
    for (int mt = 0; mt < 4; mt++) {
        int m0 = bm + wm + mt * 16 + (lane >> 2);
        float e0 = 0.f, e1 = 0.f;
#pragma unroll
        for (int nt = 0; nt < 4; nt++) {
            int n0 = bn + wn + nt * 8 + (lane & 3) * 2;
            float* p0 = C + (size_t)m0 * N + n0;
            float* p1 = C + (size_t)(m0 + 8) * N + n0;
            if (n0 < N) {
                float bv = __ldg(bias + n0);
                float v00 = acc[mt][nt][0] + bv;
                float v10 = acc[mt][nt][2] + bv;
                p0[0] = v00;
                p1[0] = v10;
                if (rowsum) { e0 += __expf(v00); e1 += __expf(v10); }
            }
            if (n0 + 1 < N) {
                float bv = __ldg(bias + n0 + 1);
                float v01 = acc[mt][nt][1] + bv;
                float v11 = acc[mt][nt][3] + bv;
                p0[1] = v01;
                p1[1] = v11;
                if (rowsum) { e0 += __expf(v01); e1 += __expf(v11); }
            }
        }
        if (rowsum) {
            e0 += __shfl_xor_sync(0xffffffffu, e0, 1);
            e0 += __shfl_xor_sync(0xffffffffu, e0, 2);
            e1 += __shfl_xor_sync(0xffffffffu, e1, 1);
            e1 += __shfl_xor_sync(0xffffffffu, e1, 2);
            if ((lane & 3) == 0) {
                atomicAdd(&rowsum[m0], e0);
                atomicAdd(&rowsum[m0 + 8], e1);
            }
        }
    }
}

// ---------------- persistent LSTM (tagged 4B h-words: data IS the flag) ----------------
// 128 blocks x 256 threads (8 warps). Warp w of block b owns unit j = 8b+w,
// all 4 gates. Lane l covers k-indices {l + 32q}. 128 fp32 weight regs/thread.
// Exchange: word[j] = (tag16 << 16) | bf16(h). Publish with st.volatile (one L2
// write); consumers poll ONE 16B volatile load (their 4 units) with immediate
// first poll + exponential nanosleep backoff (the R12-proven anti-storm fix).
// No counter, no fences: the data is the flag; <=1-step skew makes the
// ping-pong overwrite-safe (publish(t+1) requires having read ALL tags t,
// which requires every block finished reading t-1).
__global__ void __launch_bounds__(256) lstm_kernel(
    const float* __restrict__ Wf, const float* __restrict__ Wi,
    const float* __restrict__ Wg, const float* __restrict__ Wo) {
    const int b = blockIdx.x, tid = threadIdx.x;
    const int w = tid >> 5, l = tid & 31;
    const int j = b * 8 + w;

    const size_t roff = (size_t)j * (EMB + HID) + EMB;
    float wf[32], wi[32], wg[32], wo[32];
#pragma unroll
    for (int q = 0; q < 32; q++) {
        int k = l + 32 * q;
        wf[q] = Wf[roff + k];
        wi[q] = Wi[roff + k];
        wg[q] = Wg[roff + k];
        wo[q] = Wo[roff + k];
    }

    __shared__ __align__(16) float sh_h[HID];

    const float* gxp = g_Gx + (size_t)0 * (4 * HID) + j;
    float gx_f = __ldg(gxp);
    float gx_i = __ldg(gxp + HID);
    float gx_g = __ldg(gxp + 2 * HID);
    float gx_o = __ldg(gxp + 3 * HID);

    float c = 0.f;
    for (int t = 0; t < T_LEN; t++) {
        const int p = t & 1;
        // ---- poll h(t): one 16B volatile load covers this thread's 4 units ----
        {
            const unsigned* src = g_htag[p] + tid * 4;
            const unsigned want = (unsigned)t & 0xFFFFu;
            unsigned v0, v1, v2, v3;
            unsigned ns = 32;
            for (;;) {
                asm volatile("ld.volatile.global.v4.u32 {%0,%1,%2,%3}, [%4];"
                             : "=r"(v0), "=r"(v1), "=r"(v2), "=r"(v3)
                             : "l"(src) : "memory");
                if ((v0 >> 16) == want && (v1 >> 16) == want &&
                    (v2 >> 16) == want && (v3 >> 16) == want) break;
                __nanosleep(ns);
                if (ns < 256) ns <<= 1;
            }
            sh_h[tid * 4 + 0] = __uint_as_float(v0 << 16);   // bf16 -> fp32 = <<16
            sh_h[tid * 4 + 1] = __uint_as_float(v1 << 16);
            sh_h[tid * 4 + 2] = __uint_as_float(v2 << 16);
            sh_h[tid * 4 + 3] = __uint_as_float(v3 << 16);
        }
        __syncthreads();

        float sf = 0.f, si = 0.f, sg = 0.f, so = 0.f;
#pragma unroll
        for (int q = 0; q < 32; q++) {
            float h = sh_h[l + 32 * q];
            sf = fmaf(wf[q], h, sf);
            si = fmaf(wi[q], h, si);
            sg = fmaf(wg[q], h, sg);
            so = fmaf(wo[q], h, so);
        }
#pragma unroll
        for (int off = 16; off; off >>= 1) {
            sf += __shfl_xor_sync(0xffffffffu, sf, off);
            si += __shfl_xor_sync(0xffffffffu, si, off);
            sg += __shfl_xor_sync(0xffffffffu, sg, off);
            so += __shfl_xor_sync(0xffffffffu, so, off);
        }

        float fg = sigf(sf + gx_f);
        float ig = sigf(si + gx_i);
        float gg = tanhfast(sg + gx_g);
        float og = sigf(so + gx_o);
        c = fmaf(fg, c, ig * gg);
        float h = og * tanhfast(c);

        if (l == 0) {
            __nv_bfloat16 hb = __float2bfloat16(h);
            unsigned word = ((unsigned)(t + 1) << 16) |
                            (unsigned)__bfloat16_as_ushort(hb);
            asm volatile("st.volatile.global.u32 [%0], %1;"
                         :: "l"(&g_htag[p ^ 1][j]), "r"(word) : "memory");
            g_hbf[(size_t)t * HID + j] = hb;
        }

        // prefetch next step's gate-x preacts (overlaps exchange latency)
        if (t + 1 < T_LEN) {
            const float* gq = g_Gx + (size_t)(t + 1) * (4 * HID) + j;
            gx_f = __ldg(gq);
            gx_i = __ldg(gq + HID);
            gx_g = __ldg(gq + 2 * HID);
            gx_o = __ldg(gq + 3 * HID);
        }

        __syncthreads();   // protect sh_h against next iteration's poll writes
    }
}

// ---------------- log_softmax finish: subtract lse (sums precomputed in GEMM) ----------------
__global__ void logsoftmax_finish(float* __restrict__ C) {
    int r = blockIdx.x;
    float lse = __logf(g_rowsum[r]);
    float* row = C + (size_t)r * NTAG;
    for (int i = threadIdx.x; i < NTAG; i += 256) row[i] -= lse;
}

// ---------------- launch ----------------
extern "C" void kernel_launch(void* const* d_in, const int* in_sizes, int n_in,
                              void* d_out, int out_size) {
    const int*   sentence = (const int*)d_in[0];
    const float* emb  = (const float*)d_in[1];
    const float* Wf   = (const float*)d_in[2];
    const float* bf_  = (const float*)d_in[3];
    const float* Wi   = (const float*)d_in[4];
    const float* bi_  = (const float*)d_in[5];
    const float* Wg   = (const float*)d_in[6];
    const float* bg_  = (const float*)d_in[7];
    const float* Wo   = (const float*)d_in[8];
    const float* bo_  = (const float*)d_in[9];
    const float* Wt   = (const float*)d_in[10];
    const float* bt_  = (const float*)d_in[11];
    float* out = (float*)d_out;

    void *pGx, *pxbf, *pwxbf, *pbias, *pwtbf, *phbf, *prowsum;
    cudaGetSymbolAddress(&pGx, g_Gx);
    cudaGetSymbolAddress(&pxbf, g_xbf);
    cudaGetSymbolAddress(&pwxbf, g_wxbf);
    cudaGetSymbolAddress(&pbias, g_biascat);
    cudaGetSymbolAddress(&pwtbf, g_wtbf);
    cudaGetSymbolAddress(&phbf, g_hbf);
    cudaGetSymbolAddress(&prowsum, g_rowsum);

    cudaFuncSetAttribute(gemm_bf16, cudaFuncAttributeMaxDynamicSharedMemorySize, GEMM_SMEM);

    prep_all<<<16385, 256>>>(sentence, emb, Wf, Wi, Wg, Wo, bf_, bi_, bg_, bo_, Wt);

    // Gx = x @ Wx^T + b : M=4096, N=4096, K=1024 (no rowsum)
    dim3 gA((4 * HID + 127) / 128, T_LEN / 256);
    gemm_bf16<<<gA, 512, GEMM_SMEM>>>((const __nv_bfloat16*)pxbf, (const __nv_bfloat16*)pwxbf,
                                      (const float*)pbias, (float*)pGx, T_LEN, 4 * HID, EMB,
                                      nullptr);

    lstm_kernel<<<NBLK, 256>>>(Wf, Wi, Wg, Wo);

    // logits = lstm_out @ Wt^T + bt : M=4096, N=50257, K=1024 (+ fused exp-sums)
    dim3 gC((NTAG + 127) / 128, T_LEN / 256);
    gemm_bf16<<<gC, 512, GEMM_SMEM>>>((const __nv_bfloat16*)phbf, (const __nv_bfloat16*)pwtbf,
                                      bt_, out, T_LEN, NTAG, HID,
                                      (float*)prowsum);

    logsoftmax_finish<<<T_LEN, 256>>>(out);
}